// round 1
// baseline (speedup 1.0000x reference)
#include <cuda_runtime.h>
#include <cuda_bf16.h>

// Problem constants
#define B 64
#define L 512
#define T 8
#define D 1024
#define C 3
#define N_HOPS 6
#define KSPLIT 8        // split-K for the lin GEMM
#define KCHUNK (D / KSPLIT)   // 128

// ---------------- device scratch (allocation-free: __device__ globals) ----------
__device__ float g_vec[B * D];                 // current hop vector [B,D]
__device__ float g_lin_partial[KSPLIT * B * D];// split-K partials of vec@W_lin
__device__ float g_smb[B * L];                 // s_mem_base = v_loc * (emb . wa1)
__device__ float g_vloc[B * L];                // location weights
__device__ float g_aw[B * L];                  // alpha * v_loc per hop

// ---------------- kernel 1: precompute v_loc and s_mem_base ---------------------
// grid (B, L/8), 256 threads = 8 warps, one warp per l
__global__ void precompute_k(const int* __restrict__ ctx,
                             const int* __restrict__ clen,
                             const int* __restrict__ toff,
                             const float* __restrict__ emb,
                             const float* __restrict__ wattn) {
    int b = blockIdx.x;
    int l = blockIdx.y * 8 + (threadIdx.x >> 5);
    int lane = threadIdx.x & 31;
    int len = clen[b];

    float acc = 0.0f;
    float v = 0.0f;
    if (l < len) {
        int id = ctx[b * L + l];
        const float4* e4 = (const float4*)(emb + (long)id * D);
        const float4* w4 = (const float4*)wattn;  // first D floats of w_attn
        #pragma unroll
        for (int i = 0; i < 8; i++) {
            float4 e = e4[i * 32 + lane];
            float4 w = w4[i * 32 + lane];
            acc += e.x * w.x + e.y * w.y + e.z * w.z + e.w * w.w;
        }
        #pragma unroll
        for (int o = 16; o > 0; o >>= 1)
            acc += __shfl_xor_sync(0xffffffffu, acc, o);
        v = 1.0f - fabsf((float)(l - toff[b])) / (float)len;
    }
    if (lane == 0) {
        g_vloc[b * L + l] = v;
        g_smb[b * L + l] = v * acc;   // 0 when masked (matches reference path)
    }
}

// ---------------- kernel 2: v_aspect -> g_vec -----------------------------------
// grid B, 256 threads, float4 per thread (256*4 = 1024 = D)
__global__ void vaspect_k(const int* __restrict__ tgt,
                          const int* __restrict__ tlen,
                          const float* __restrict__ emb) {
    int b = blockIdx.x, t = threadIdx.x;
    int n = tlen[b];
    float4 acc = make_float4(0.f, 0.f, 0.f, 0.f);
    #pragma unroll
    for (int i = 0; i < T; i++) {
        if (i < n) {
            int id = tgt[b * T + i];
            float4 e = ((const float4*)(emb + (long)id * D))[t];
            acc.x += e.x; acc.y += e.y; acc.z += e.z; acc.w += e.w;
        }
    }
    float inv = 1.0f / (float)n;
    acc.x *= inv; acc.y *= inv; acc.z *= inv; acc.w *= inv;
    ((float4*)(g_vec + b * D))[t] = acc;
}

// ---------------- kernel 3: per-hop scores + softmax -> g_aw --------------------
// grid B, 512 threads (one per l)
__global__ void softmax_k(const float* __restrict__ wattn,
                          const float* __restrict__ battn,
                          const int* __restrict__ clen) {
    int b = blockIdx.x, t = threadIdx.x;
    __shared__ float red[L];
    const float* wa2 = wattn + D;

    // s_vec = vec . wa2 (1024 elems over 512 threads)
    float p = g_vec[b * D + t] * wa2[t] + g_vec[b * D + 512 + t] * wa2[512 + t];
    red[t] = p;
    __syncthreads();
    #pragma unroll
    for (int s = 256; s > 0; s >>= 1) {
        if (t < s) red[t] += red[t + s];
        __syncthreads();
    }
    float svec = red[0] + battn[0];
    __syncthreads();

    int len = clen[b];
    float sc = (t < len) ? tanhf(g_smb[b * L + t] + svec) : -1e30f;

    // max reduce
    red[t] = sc;
    __syncthreads();
    #pragma unroll
    for (int s = 256; s > 0; s >>= 1) {
        if (t < s) red[t] = fmaxf(red[t], red[t + s]);
        __syncthreads();
    }
    float mx = red[0];
    __syncthreads();

    float e = expf(sc - mx);   // masked lanes: expf(~-1e30) -> 0
    red[t] = e;
    __syncthreads();
    #pragma unroll
    for (int s = 256; s > 0; s >>= 1) {
        if (t < s) red[t] += red[t + s];
        __syncthreads();
    }
    float sm = red[0];

    g_aw[b * L + t] = (e / sm) * g_vloc[b * L + t];
}

// ---------------- kernel 4: lin GEMM (split-K) ----------------------------------
// C_partial[ks][64][1024] = vec[64, kchunk] @ W_lin[kchunk, 1024]
// grid (D/64 = 16, KSPLIT = 8), 256 threads, 64x64 tile, 4x4 per thread
__global__ void lin_gemm_k(const float* __restrict__ Wlin) {
    __shared__ float As[16][65];   // [kk][m], padded
    __shared__ float Bs[16][64];   // [kk][n]
    int tid = threadIdx.x;
    int tx = tid & 15, ty = tid >> 4;
    int n0 = blockIdx.x * 64;
    int kbase = blockIdx.y * KCHUNK;

    float acc[4][4] = {};
    for (int k0 = 0; k0 < KCHUNK; k0 += 16) {
        // load A tile: vec[m][kbase+k0 + kq..kq+3]
        {
            int m = tid >> 2;
            int kq = (tid & 3) << 2;
            float4 av = *(const float4*)&g_vec[m * D + kbase + k0 + kq];
            As[kq + 0][m] = av.x;
            As[kq + 1][m] = av.y;
            As[kq + 2][m] = av.z;
            As[kq + 3][m] = av.w;
        }
        // load B tile: W[(kbase+k0+row)][n0 + c4..c4+3]
        {
            int row = tid >> 4;
            int c4 = (tid & 15) << 2;
            float4 bv = *(const float4*)&Wlin[(long)(kbase + k0 + row) * D + n0 + c4];
            *(float4*)&Bs[row][c4] = bv;
        }
        __syncthreads();
        #pragma unroll
        for (int kk = 0; kk < 16; kk++) {
            float a[4], bb[4];
            #pragma unroll
            for (int i = 0; i < 4; i++) a[i] = As[kk][ty * 4 + i];
            float4 bv = *(const float4*)&Bs[kk][tx * 4];
            bb[0] = bv.x; bb[1] = bv.y; bb[2] = bv.z; bb[3] = bv.w;
            #pragma unroll
            for (int i = 0; i < 4; i++)
                #pragma unroll
                for (int j = 0; j < 4; j++)
                    acc[i][j] += a[i] * bb[j];
        }
        __syncthreads();
    }
    int ks = blockIdx.y;
    #pragma unroll
    for (int i = 0; i < 4; i++) {
        int m = ty * 4 + i;
        #pragma unroll
        for (int j = 0; j < 4; j++) {
            g_lin_partial[((long)ks * B + m) * D + n0 + tx * 4 + j] = acc[i][j];
        }
    }
}

// ---------------- kernel 5: attention reduce + lin epilogue -> new g_vec --------
// grid (B, 4), 128 threads, each thread owns 2 consecutive d (dchunk = 256)
__global__ void attn_k(const int* __restrict__ ctx,
                       const int* __restrict__ clen,
                       const float* __restrict__ emb,
                       const float* __restrict__ blin) {
    int b = blockIdx.x;
    int tid = threadIdx.x;
    __shared__ float aw[L];
    __shared__ int ids[L];
    for (int i = tid; i < L; i += 128) {
        aw[i] = g_aw[b * L + i];
        ids[i] = ctx[b * L + i];
    }
    __syncthreads();

    int len = clen[b];
    int d0 = blockIdx.y * 256 + tid * 2;
    float ax = 0.f, ay = 0.f;
    #pragma unroll 8
    for (int l = 0; l < len; l++) {
        float w = aw[l];
        float2 v = *(const float2*)(emb + (long)ids[l] * D + d0);
        ax += w * v.x;
        ay += w * v.y;
    }
    // epilogue: add lin = sum of split-K partials + b_lin
    float lx = blin[d0], ly = blin[d0 + 1];
    #pragma unroll
    for (int s = 0; s < KSPLIT; s++) {
        float2 p = *(const float2*)(g_lin_partial + ((long)s * B + b) * D + d0);
        lx += p.x;
        ly += p.y;
    }
    g_vec[b * D + d0] = ax + lx;
    g_vec[b * D + d0 + 1] = ay + ly;
}

// ---------------- kernel 6: output logits ---------------------------------------
// grid B, 128 threads
__global__ void out_k(const float* __restrict__ Wout,
                      const float* __restrict__ bout,
                      float* __restrict__ out) {
    int b = blockIdx.x, t = threadIdx.x;
    float p0 = 0.f, p1 = 0.f, p2 = 0.f;
    for (int d = t; d < D; d += 128) {
        float v = g_vec[b * D + d];
        p0 += v * Wout[d * C + 0];
        p1 += v * Wout[d * C + 1];
        p2 += v * Wout[d * C + 2];
    }
    __shared__ float r[C][128];
    r[0][t] = p0; r[1][t] = p1; r[2][t] = p2;
    __syncthreads();
    #pragma unroll
    for (int s = 64; s > 0; s >>= 1) {
        if (t < s) {
            r[0][t] += r[0][t + s];
            r[1][t] += r[1][t + s];
            r[2][t] += r[2][t + s];
        }
        __syncthreads();
    }
    if (t < C) out[b * C + t] = r[t][0] + bout[t];
}

// ---------------- launcher -------------------------------------------------------
extern "C" void kernel_launch(void* const* d_in, const int* in_sizes, int n_in,
                              void* d_out, int out_size) {
    const int*   ctx   = (const int*)d_in[0];
    const int*   tgt   = (const int*)d_in[1];
    const int*   clen  = (const int*)d_in[2];
    const int*   tlen  = (const int*)d_in[3];
    const int*   toff  = (const int*)d_in[4];
    const float* emb   = (const float*)d_in[5];
    const float* Wlin  = (const float*)d_in[6];
    const float* blin  = (const float*)d_in[7];
    const float* wattn = (const float*)d_in[8];
    const float* battn = (const float*)d_in[9];
    const float* Wout  = (const float*)d_in[10];
    const float* bout  = (const float*)d_in[11];
    float* out = (float*)d_out;

    precompute_k<<<dim3(B, L / 8), 256>>>(ctx, clen, toff, emb, wattn);
    vaspect_k<<<B, 256>>>(tgt, tlen, emb);

    for (int h = 0; h < N_HOPS; h++) {
        softmax_k<<<B, L>>>(wattn, battn, clen);
        lin_gemm_k<<<dim3(D / 64, KSPLIT), 256>>>(Wlin);
        attn_k<<<dim3(B, 4), 128>>>(ctx, clen, emb, blin);
    }

    out_k<<<B, 128>>>(Wout, bout, out);
}

// round 2
// speedup vs baseline: 1.6122x; 1.6122x over previous
#include <cuda_runtime.h>
#include <cuda_bf16.h>

// Problem constants
#define B 64
#define L 512
#define T 8
#define D 1024
#define C 3
#define N_HOPS 6
#define KSPLIT 32
#define KCHUNK (D / KSPLIT)   // 32
#define LS 8                  // l-splits for attention
#define LCHUNK (L / LS)       // 64

// ---------------- device scratch ----------------
__device__ float g_vec[B * D];                   // current hop vector [B,D]
__device__ float g_lin_partial[KSPLIT * B * D];  // split-K partials of vec@W_lin
__device__ float g_attn_partial[LS * B * D];     // split-L partials of attention
__device__ float g_smb[B * L];                   // s_mem_base = v_loc * (emb . wa1)
__device__ float g_vloc[B * L];                  // location weights
__device__ float g_aw[B * L];                    // alpha * v_loc per hop
__device__ float g_svec[B];                      // vec . w_attn[D:]

// ---------------- kernel 1: precompute v_loc and s_mem_base ---------------------
// grid (B, L/8), 256 threads = 8 warps, one warp per l
__global__ void precompute_k(const int* __restrict__ ctx,
                             const int* __restrict__ clen,
                             const int* __restrict__ toff,
                             const float* __restrict__ emb,
                             const float* __restrict__ wattn) {
    int b = blockIdx.x;
    int l = blockIdx.y * 8 + (threadIdx.x >> 5);
    int lane = threadIdx.x & 31;
    int len = clen[b];

    float acc = 0.0f;
    float v = 0.0f;
    if (l < len) {
        int id = ctx[b * L + l];
        const float4* e4 = (const float4*)(emb + (long)id * D);
        const float4* w4 = (const float4*)wattn;
        #pragma unroll
        for (int i = 0; i < 8; i++) {
            float4 e = e4[i * 32 + lane];
            float4 w = w4[i * 32 + lane];
            acc += e.x * w.x + e.y * w.y + e.z * w.z + e.w * w.w;
        }
        #pragma unroll
        for (int o = 16; o > 0; o >>= 1)
            acc += __shfl_xor_sync(0xffffffffu, acc, o);
        v = 1.0f - fabsf((float)(l - toff[b])) / (float)len;
    }
    if (lane == 0) {
        g_vloc[b * L + l] = v;
        g_smb[b * L + l] = v * acc;
    }
}

// ---------------- kernel 2: v_aspect -> g_vec, also g_svec ----------------------
// grid B, 256 threads, float4 per thread
__global__ void vaspect_k(const int* __restrict__ tgt,
                          const int* __restrict__ tlen,
                          const float* __restrict__ emb,
                          const float* __restrict__ wattn) {
    int b = blockIdx.x, t = threadIdx.x;
    int n = tlen[b];
    float4 acc = make_float4(0.f, 0.f, 0.f, 0.f);
    #pragma unroll
    for (int i = 0; i < T; i++) {
        if (i < n) {
            int id = tgt[b * T + i];
            float4 e = ((const float4*)(emb + (long)id * D))[t];
            acc.x += e.x; acc.y += e.y; acc.z += e.z; acc.w += e.w;
        }
    }
    float inv = 1.0f / (float)n;
    acc.x *= inv; acc.y *= inv; acc.z *= inv; acc.w *= inv;
    ((float4*)(g_vec + b * D))[t] = acc;

    // svec partial: dot with wa2
    float4 w = ((const float4*)(wattn + D))[t];
    float p = acc.x * w.x + acc.y * w.y + acc.z * w.z + acc.w * w.w;
    __shared__ float red[256];
    red[t] = p;
    __syncthreads();
    #pragma unroll
    for (int s = 128; s > 0; s >>= 1) {
        if (t < s) red[t] += red[t + s];
        __syncthreads();
    }
    if (t == 0) g_svec[b] = red[0];
}

// ---------------- kernel 3: per-hop scores + softmax -> g_aw --------------------
// grid B, 512 threads (one per l)
__global__ void softmax_k(const float* __restrict__ battn,
                          const int* __restrict__ clen) {
    int b = blockIdx.x, t = threadIdx.x;
    __shared__ float red[L];

    float svec = g_svec[b] + battn[0];
    int len = clen[b];
    float sc = (t < len) ? tanhf(g_smb[b * L + t] + svec) : -1e30f;

    red[t] = sc;
    __syncthreads();
    #pragma unroll
    for (int s = 256; s > 0; s >>= 1) {
        if (t < s) red[t] = fmaxf(red[t], red[t + s]);
        __syncthreads();
    }
    float mx = red[0];
    __syncthreads();

    float e = expf(sc - mx);
    red[t] = e;
    __syncthreads();
    #pragma unroll
    for (int s = 256; s > 0; s >>= 1) {
        if (t < s) red[t] += red[t + s];
        __syncthreads();
    }
    float sm = red[0];

    g_aw[b * L + t] = (e / sm) * g_vloc[b * L + t];
}

// ---------------- kernel 4: lin GEMM (split-K 32) --------------------------------
// grid (D/64 = 16, KSPLIT = 32), 256 threads, 64x64 tile, 4x4 per thread
__global__ void lin_gemm_k(const float* __restrict__ Wlin) {
    __shared__ float As[16][65];
    __shared__ float Bs[16][64];
    int tid = threadIdx.x;
    int tx = tid & 15, ty = tid >> 4;
    int n0 = blockIdx.x * 64;
    int kbase = blockIdx.y * KCHUNK;

    float acc[4][4] = {};
    #pragma unroll
    for (int k0 = 0; k0 < KCHUNK; k0 += 16) {
        {
            int m = tid >> 2;
            int kq = (tid & 3) << 2;
            float4 av = *(const float4*)&g_vec[m * D + kbase + k0 + kq];
            As[kq + 0][m] = av.x;
            As[kq + 1][m] = av.y;
            As[kq + 2][m] = av.z;
            As[kq + 3][m] = av.w;
        }
        {
            int row = tid >> 4;
            int c4 = (tid & 15) << 2;
            float4 bv = *(const float4*)&Wlin[(long)(kbase + k0 + row) * D + n0 + c4];
            *(float4*)&Bs[row][c4] = bv;
        }
        __syncthreads();
        #pragma unroll
        for (int kk = 0; kk < 16; kk++) {
            float a[4], bb[4];
            #pragma unroll
            for (int i = 0; i < 4; i++) a[i] = As[kk][ty * 4 + i];
            float4 bv = *(const float4*)&Bs[kk][tx * 4];
            bb[0] = bv.x; bb[1] = bv.y; bb[2] = bv.z; bb[3] = bv.w;
            #pragma unroll
            for (int i = 0; i < 4; i++)
                #pragma unroll
                for (int j = 0; j < 4; j++)
                    acc[i][j] += a[i] * bb[j];
        }
        __syncthreads();
    }
    int ks = blockIdx.y;
    #pragma unroll
    for (int i = 0; i < 4; i++) {
        int m = ty * 4 + i;
        #pragma unroll
        for (int j = 0; j < 4; j++) {
            g_lin_partial[((long)ks * B + m) * D + n0 + tx * 4 + j] = acc[i][j];
        }
    }
}

// ---------------- kernel 5: attention partials (split L) -------------------------
// grid (B, 2, LS=8), 128 threads, each thread float4 (d-chunk 512)
__global__ void attn_part_k(const int* __restrict__ ctx,
                            const int* __restrict__ clen,
                            const float* __restrict__ emb) {
    int b = blockIdx.x;
    int dch = blockIdx.y;
    int ls = blockIdx.z;
    int tid = threadIdx.x;

    __shared__ float aw[LCHUNK];
    __shared__ int ids[LCHUNK];
    int l0 = ls * LCHUNK;
    if (tid < LCHUNK) {
        aw[tid] = g_aw[b * L + l0 + tid];
        ids[tid] = ctx[b * L + l0 + tid];
    }
    __syncthreads();

    int len = clen[b];
    int lend = len - l0;
    if (lend > LCHUNK) lend = LCHUNK;

    int d0 = dch * 512 + tid * 4;
    float4 acc = make_float4(0.f, 0.f, 0.f, 0.f);
    #pragma unroll 4
    for (int i = 0; i < lend; i++) {
        float w = aw[i];
        float4 v = *(const float4*)(emb + (long)ids[i] * D + d0);
        acc.x += w * v.x;
        acc.y += w * v.y;
        acc.z += w * v.z;
        acc.w += w * v.w;
    }
    *(float4*)(g_attn_partial + ((long)ls * B + b) * D + d0) = acc;
}

// ---------------- kernel 6: combine partials -> new g_vec, new g_svec ------------
// grid B, 256 threads, float4 per thread
__global__ void combine_k(const float* __restrict__ blin,
                          const float* __restrict__ wattn) {
    int b = blockIdx.x, t = threadIdx.x;
    int d = t * 4;
    float4 v = *(const float4*)(blin + d);
    #pragma unroll
    for (int ls = 0; ls < LS; ls++) {
        float4 p = *(const float4*)(g_attn_partial + ((long)ls * B + b) * D + d);
        v.x += p.x; v.y += p.y; v.z += p.z; v.w += p.w;
    }
    #pragma unroll
    for (int ks = 0; ks < KSPLIT; ks++) {
        float4 p = *(const float4*)(g_lin_partial + ((long)ks * B + b) * D + d);
        v.x += p.x; v.y += p.y; v.z += p.z; v.w += p.w;
    }
    *(float4*)(g_vec + b * D + d) = v;

    // svec = new vec . wa2
    float4 w = ((const float4*)(wattn + D))[t];
    float p = v.x * w.x + v.y * w.y + v.z * w.z + v.w * w.w;
    __shared__ float red[256];
    red[t] = p;
    __syncthreads();
    #pragma unroll
    for (int s = 128; s > 0; s >>= 1) {
        if (t < s) red[t] += red[t + s];
        __syncthreads();
    }
    if (t == 0) g_svec[b] = red[0];
}

// ---------------- kernel 7: output logits ---------------------------------------
__global__ void out_k(const float* __restrict__ Wout,
                      const float* __restrict__ bout,
                      float* __restrict__ out) {
    int b = blockIdx.x, t = threadIdx.x;
    float p0 = 0.f, p1 = 0.f, p2 = 0.f;
    for (int d = t; d < D; d += 128) {
        float v = g_vec[b * D + d];
        p0 += v * Wout[d * C + 0];
        p1 += v * Wout[d * C + 1];
        p2 += v * Wout[d * C + 2];
    }
    __shared__ float r[C][128];
    r[0][t] = p0; r[1][t] = p1; r[2][t] = p2;
    __syncthreads();
    #pragma unroll
    for (int s = 64; s > 0; s >>= 1) {
        if (t < s) {
            r[0][t] += r[0][t + s];
            r[1][t] += r[1][t + s];
            r[2][t] += r[2][t + s];
        }
        __syncthreads();
    }
    if (t < C) out[b * C + t] = r[t][0] + bout[t];
}

// ---------------- launcher -------------------------------------------------------
extern "C" void kernel_launch(void* const* d_in, const int* in_sizes, int n_in,
                              void* d_out, int out_size) {
    const int*   ctx   = (const int*)d_in[0];
    const int*   tgt   = (const int*)d_in[1];
    const int*   clen  = (const int*)d_in[2];
    const int*   tlen  = (const int*)d_in[3];
    const int*   toff  = (const int*)d_in[4];
    const float* emb   = (const float*)d_in[5];
    const float* Wlin  = (const float*)d_in[6];
    const float* blin  = (const float*)d_in[7];
    const float* wattn = (const float*)d_in[8];
    const float* battn = (const float*)d_in[9];
    const float* Wout  = (const float*)d_in[10];
    const float* bout  = (const float*)d_in[11];
    float* out = (float*)d_out;

    precompute_k<<<dim3(B, L / 8), 256>>>(ctx, clen, toff, emb, wattn);
    vaspect_k<<<B, 256>>>(tgt, tlen, emb, wattn);

    for (int h = 0; h < N_HOPS; h++) {
        softmax_k<<<B, L>>>(battn, clen);
        lin_gemm_k<<<dim3(D / 64, KSPLIT), 256>>>(Wlin);
        attn_part_k<<<dim3(B, 2, LS), 128>>>(ctx, clen, emb);
        combine_k<<<B, 256>>>(blin, wattn);
    }

    out_k<<<B, 128>>>(Wout, bout, out);
}

// round 3
// speedup vs baseline: 2.5655x; 1.5913x over previous
#include <cuda_runtime.h>
#include <cuda_bf16.h>

// Problem constants
#define B 64
#define L 512
#define T 8
#define D 1024
#define C 3
#define N_HOPS 6
#define KSPLIT 32
#define KCHUNK (D / KSPLIT)   // 32
#define LS 8                  // l-splits for attention
#define LCHUNK (L / LS)       // 64
#define NATTN (B * LS)        // 512 attention blocks
#define NLIN (16 * KSPLIT)    // 512 lin blocks

// ---------------- device scratch ----------------
__device__ float g_vec[B * D];                   // current hop vector [B,D]
__device__ float g_lin_partial[KSPLIT * B * D];  // split-K partials of vec@W_lin
__device__ float g_attn_partial[LS * B * D];     // split-L partials of attention
__device__ float g_smb[B * L];                   // s_mem_base = v_loc * (emb . wa1)
__device__ float g_vloc[B * L];                  // location weights
__device__ float g_aw[B * L];                    // alpha * v_loc per hop
__device__ float g_svec[B];                      // vec . w_attn[D:]

// ---------------- kernel 1: precompute v_loc and s_mem_base ---------------------
__global__ void precompute_k(const int* __restrict__ ctx,
                             const int* __restrict__ clen,
                             const int* __restrict__ toff,
                             const float* __restrict__ emb,
                             const float* __restrict__ wattn) {
    int b = blockIdx.x;
    int l = blockIdx.y * 8 + (threadIdx.x >> 5);
    int lane = threadIdx.x & 31;
    int len = clen[b];

    float acc = 0.0f;
    float v = 0.0f;
    if (l < len) {
        int id = ctx[b * L + l];
        const float4* e4 = (const float4*)(emb + (long)id * D);
        const float4* w4 = (const float4*)wattn;
        #pragma unroll
        for (int i = 0; i < 8; i++) {
            float4 e = e4[i * 32 + lane];
            float4 w = w4[i * 32 + lane];
            acc += e.x * w.x + e.y * w.y + e.z * w.z + e.w * w.w;
        }
        #pragma unroll
        for (int o = 16; o > 0; o >>= 1)
            acc += __shfl_xor_sync(0xffffffffu, acc, o);
        v = 1.0f - fabsf((float)(l - toff[b])) / (float)len;
    }
    if (lane == 0) {
        g_vloc[b * L + l] = v;
        g_smb[b * L + l] = v * acc;
    }
}

// ---------------- kernel 2: v_aspect -> g_vec, also g_svec ----------------------
__global__ void vaspect_k(const int* __restrict__ tgt,
                          const int* __restrict__ tlen,
                          const float* __restrict__ emb,
                          const float* __restrict__ wattn) {
    int b = blockIdx.x, t = threadIdx.x;
    int n = tlen[b];
    float4 acc = make_float4(0.f, 0.f, 0.f, 0.f);
    #pragma unroll
    for (int i = 0; i < T; i++) {
        if (i < n) {
            int id = tgt[b * T + i];
            float4 e = ((const float4*)(emb + (long)id * D))[t];
            acc.x += e.x; acc.y += e.y; acc.z += e.z; acc.w += e.w;
        }
    }
    float inv = 1.0f / (float)n;
    acc.x *= inv; acc.y *= inv; acc.z *= inv; acc.w *= inv;
    ((float4*)(g_vec + b * D))[t] = acc;

    float4 w = ((const float4*)(wattn + D))[t];
    float p = acc.x * w.x + acc.y * w.y + acc.z * w.z + acc.w * w.w;
    __shared__ float red[256];
    red[t] = p;
    __syncthreads();
    #pragma unroll
    for (int s = 128; s > 0; s >>= 1) {
        if (t < s) red[t] += red[t + s];
        __syncthreads();
    }
    if (t == 0) g_svec[b] = red[0];
}

// ---------------- softmax core (device inline) ----------------------------------
__device__ __forceinline__ void softmax_core(int b, int t, float svec, int len,
                                             float* red) {
    float sc = (t < len) ? tanhf(g_smb[b * L + t] + svec) : -1e30f;
    red[t] = sc;
    __syncthreads();
    #pragma unroll
    for (int s = 256; s > 0; s >>= 1) {
        if (t < s) red[t] = fmaxf(red[t], red[t + s]);
        __syncthreads();
    }
    float mx = red[0];
    __syncthreads();
    float e = expf(sc - mx);
    red[t] = e;
    __syncthreads();
    #pragma unroll
    for (int s = 256; s > 0; s >>= 1) {
        if (t < s) red[t] += red[t + s];
        __syncthreads();
    }
    float sm = red[0];
    g_aw[b * L + t] = (e / sm) * g_vloc[b * L + t];
}

// ---------------- kernel 3: standalone softmax (hop 0) --------------------------
__global__ void softmax_k(const float* __restrict__ battn,
                          const int* __restrict__ clen) {
    int b = blockIdx.x, t = threadIdx.x;
    __shared__ float red[L];
    softmax_core(b, t, g_svec[b] + battn[0], clen[b], red);
}

// ---------------- kernel 4: FUSED work: attn partials + lin GEMM ----------------
// grid NATTN + NLIN blocks, 256 threads.
// blocks [0, NATTN): attention; blocks [NATTN, NATTN+NLIN): lin split-K GEMM
__global__ void work_k(const int* __restrict__ ctx,
                       const int* __restrict__ clen,
                       const float* __restrict__ emb,
                       const float* __restrict__ Wlin) {
    __shared__ float sh[16 * 65 + 16 * 64];   // lin tiles; attn reuses front
    int bid = blockIdx.x;
    int tid = threadIdx.x;

    if (bid < NATTN) {
        // ---- attention role: block = (b, ls), full D, float4/thread ----
        int b = bid & (B - 1);
        int ls = bid >> 6;           // bid / B
        float* aw = sh;              // [LCHUNK]
        int* ids = (int*)(sh + LCHUNK);
        int l0 = ls * LCHUNK;
        if (tid < LCHUNK) {
            aw[tid] = g_aw[b * L + l0 + tid];
            ids[tid] = ctx[b * L + l0 + tid];
        }
        __syncthreads();

        int len = clen[b];
        int lend = len - l0;
        if (lend > LCHUNK) lend = LCHUNK;

        int d0 = tid * 4;
        float4 acc = make_float4(0.f, 0.f, 0.f, 0.f);
        #pragma unroll 8
        for (int i = 0; i < lend; i++) {
            float w = aw[i];
            float4 v = *(const float4*)(emb + (long)ids[i] * D + d0);
            acc.x += w * v.x;
            acc.y += w * v.y;
            acc.z += w * v.z;
            acc.w += w * v.w;
        }
        *(float4*)(g_attn_partial + ((long)ls * B + b) * D + d0) = acc;
    } else {
        // ---- lin GEMM role: 64x64 tile, split-K ----
        int lb = bid - NATTN;
        int n0 = (lb & 15) * 64;
        int ks = lb >> 4;
        int kbase = ks * KCHUNK;
        float (*As)[65] = (float(*)[65])sh;
        float (*Bs)[64] = (float(*)[64])(sh + 16 * 65);
        int tx = tid & 15, ty = tid >> 4;

        float acc[4][4] = {};
        #pragma unroll
        for (int k0 = 0; k0 < KCHUNK; k0 += 16) {
            {
                int m = tid >> 2;
                int kq = (tid & 3) << 2;
                float4 av = *(const float4*)&g_vec[m * D + kbase + k0 + kq];
                As[kq + 0][m] = av.x;
                As[kq + 1][m] = av.y;
                As[kq + 2][m] = av.z;
                As[kq + 3][m] = av.w;
            }
            {
                int row = tid >> 4;
                int c4 = (tid & 15) << 2;
                float4 bv = *(const float4*)&Wlin[(long)(kbase + k0 + row) * D + n0 + c4];
                *(float4*)&Bs[row][c4] = bv;
            }
            __syncthreads();
            #pragma unroll
            for (int kk = 0; kk < 16; kk++) {
                float a[4], bb[4];
                #pragma unroll
                for (int i = 0; i < 4; i++) a[i] = As[kk][ty * 4 + i];
                float4 bv = *(const float4*)&Bs[kk][tx * 4];
                bb[0] = bv.x; bb[1] = bv.y; bb[2] = bv.z; bb[3] = bv.w;
                #pragma unroll
                for (int i = 0; i < 4; i++)
                    #pragma unroll
                    for (int j = 0; j < 4; j++)
                        acc[i][j] += a[i] * bb[j];
            }
            __syncthreads();
        }
        #pragma unroll
        for (int i = 0; i < 4; i++) {
            int m = ty * 4 + i;
            #pragma unroll
            for (int j = 0; j < 4; j++) {
                g_lin_partial[((long)ks * B + m) * D + n0 + tx * 4 + j] = acc[i][j];
            }
        }
    }
}

// ---------------- combine core: partials -> vec (2 floats per thread) -----------
__device__ __forceinline__ float2 combine_core(int b, int t, const float* blin) {
    int d = t * 2;
    float2 v = *(const float2*)(blin + d);
    #pragma unroll
    for (int ls = 0; ls < LS; ls++) {
        float2 p = *(const float2*)(g_attn_partial + ((long)ls * B + b) * D + d);
        v.x += p.x; v.y += p.y;
    }
    #pragma unroll
    for (int ks = 0; ks < KSPLIT; ks++) {
        float2 p = *(const float2*)(g_lin_partial + ((long)ks * B + b) * D + d);
        v.x += p.x; v.y += p.y;
    }
    *(float2*)(g_vec + b * D + d) = v;
    return v;
}

// ---------------- kernel 5: fused combine + softmax (hops 0..4) -----------------
// grid B, 512 threads
__global__ void combine_softmax_k(const float* __restrict__ blin,
                                  const float* __restrict__ wattn,
                                  const float* __restrict__ battn,
                                  const int* __restrict__ clen) {
    int b = blockIdx.x, t = threadIdx.x;
    __shared__ float red[L];

    float2 v = combine_core(b, t, blin);

    // svec = vec . wa2
    int d = t * 2;
    float2 w = *(const float2*)(wattn + D + d);
    red[t] = v.x * w.x + v.y * w.y;
    __syncthreads();
    #pragma unroll
    for (int s = 256; s > 0; s >>= 1) {
        if (t < s) red[t] += red[t + s];
        __syncthreads();
    }
    float svec = red[0] + battn[0];
    __syncthreads();

    softmax_core(b, t, svec, clen[b], red);
}

// ---------------- kernel 6: fused combine + output logits (last hop) ------------
// grid B, 512 threads
__global__ void combine_out_k(const float* __restrict__ blin,
                              const float* __restrict__ Wout,
                              const float* __restrict__ bout,
                              float* __restrict__ out) {
    int b = blockIdx.x, t = threadIdx.x;
    float2 v = combine_core(b, t, blin);

    int d = t * 2;
    float p0 = v.x * Wout[d * C + 0] + v.y * Wout[(d + 1) * C + 0];
    float p1 = v.x * Wout[d * C + 1] + v.y * Wout[(d + 1) * C + 1];
    float p2 = v.x * Wout[d * C + 2] + v.y * Wout[(d + 1) * C + 2];

    __shared__ float r[C][512];
    r[0][t] = p0; r[1][t] = p1; r[2][t] = p2;
    __syncthreads();
    #pragma unroll
    for (int s = 256; s > 0; s >>= 1) {
        if (t < s) {
            r[0][t] += r[0][t + s];
            r[1][t] += r[1][t + s];
            r[2][t] += r[2][t + s];
        }
        __syncthreads();
    }
    if (t < C) out[b * C + t] = r[t][0] + bout[t];
}

// ---------------- launcher -------------------------------------------------------
extern "C" void kernel_launch(void* const* d_in, const int* in_sizes, int n_in,
                              void* d_out, int out_size) {
    const int*   ctx   = (const int*)d_in[0];
    const int*   tgt   = (const int*)d_in[1];
    const int*   clen  = (const int*)d_in[2];
    const int*   tlen  = (const int*)d_in[3];
    const int*   toff  = (const int*)d_in[4];
    const float* emb   = (const float*)d_in[5];
    const float* Wlin  = (const float*)d_in[6];
    const float* blin  = (const float*)d_in[7];
    const float* wattn = (const float*)d_in[8];
    const float* battn = (const float*)d_in[9];
    const float* Wout  = (const float*)d_in[10];
    const float* bout  = (const float*)d_in[11];
    float* out = (float*)d_out;

    precompute_k<<<dim3(B, L / 8), 256>>>(ctx, clen, toff, emb, wattn);
    vaspect_k<<<B, 256>>>(tgt, tlen, emb, wattn);
    softmax_k<<<B, L>>>(battn, clen);

    for (int h = 0; h < N_HOPS; h++) {
        work_k<<<NATTN + NLIN, 256>>>(ctx, clen, emb, Wlin);
        if (h < N_HOPS - 1)
            combine_softmax_k<<<B, L>>>(blin, wattn, battn, clen);
        else
            combine_out_k<<<B, L>>>(blin, Wout, bout, out);
    }
}

// round 4
// speedup vs baseline: 2.7231x; 1.0614x over previous
#include <cuda_runtime.h>
#include <cuda_bf16.h>

// Problem constants
#define B 64
#define L 512
#define T 8
#define D 1024
#define C 3
#define N_HOPS 6
#define KSPLIT 16
#define KCHUNK (D / KSPLIT)   // 64
#define LS 8                  // l-splits for attention
#define LCHUNK (L / LS)       // 64
#define NATTN (B * LS)        // 512 attention blocks
#define NLIN (16 * KSPLIT)    // 256 lin blocks

// ---------------- device scratch ----------------
__device__ __nv_bfloat16 g_mem[(size_t)B * L * D]; // staged context embeddings (64 MB)
__device__ float g_vec[B * D];                     // current hop vector [B,D]
__device__ float g_lin_partial[KSPLIT * B * D];    // split-K partials of vec@W_lin
__device__ float g_attn_partial[LS * B * D];       // split-L partials of attention
__device__ float g_smb[B * L];                     // s_mem_base = v_loc * (emb . wa1)
__device__ float g_vloc[B * L];                    // location weights
__device__ float g_aw[B * L];                      // alpha * v_loc per hop
__device__ float g_svec[B];                        // vec . w_attn[D:]

// ---------------- kernel 1: precompute v_loc, s_mem_base, stage bf16 memory -----
// grid (B, L/8), 256 threads = 8 warps, one warp per l
__global__ void precompute_k(const int* __restrict__ ctx,
                             const int* __restrict__ clen,
                             const int* __restrict__ toff,
                             const float* __restrict__ emb,
                             const float* __restrict__ wattn) {
    int b = blockIdx.x;
    int l = blockIdx.y * 8 + (threadIdx.x >> 5);
    int lane = threadIdx.x & 31;
    int len = clen[b];

    float acc = 0.0f;
    float v = 0.0f;
    if (l < len) {
        int id = ctx[b * L + l];
        const float4* e4 = (const float4*)(emb + (long)id * D);
        const float4* w4 = (const float4*)wattn;
        uint2* dst = (uint2*)(g_mem + (size_t)(b * L + l) * D);
        #pragma unroll
        for (int i = 0; i < 8; i++) {
            float4 e = e4[i * 32 + lane];
            float4 w = w4[i * 32 + lane];
            acc += e.x * w.x + e.y * w.y + e.z * w.z + e.w * w.w;
            union { uint2 u; __nv_bfloat162 h[2]; } pk;
            pk.h[0] = __floats2bfloat162_rn(e.x, e.y);
            pk.h[1] = __floats2bfloat162_rn(e.z, e.w);
            dst[i * 32 + lane] = pk.u;
        }
        #pragma unroll
        for (int o = 16; o > 0; o >>= 1)
            acc += __shfl_xor_sync(0xffffffffu, acc, o);
        v = 1.0f - fabsf((float)(l - toff[b])) / (float)len;
    }
    if (lane == 0) {
        g_vloc[b * L + l] = v;
        g_smb[b * L + l] = v * acc;
    }
}

// ---------------- kernel 2: v_aspect -> g_vec, also g_svec ----------------------
__global__ void vaspect_k(const int* __restrict__ tgt,
                          const int* __restrict__ tlen,
                          const float* __restrict__ emb,
                          const float* __restrict__ wattn) {
    int b = blockIdx.x, t = threadIdx.x;
    int n = tlen[b];
    float4 acc = make_float4(0.f, 0.f, 0.f, 0.f);
    #pragma unroll
    for (int i = 0; i < T; i++) {
        if (i < n) {
            int id = tgt[b * T + i];
            float4 e = ((const float4*)(emb + (long)id * D))[t];
            acc.x += e.x; acc.y += e.y; acc.z += e.z; acc.w += e.w;
        }
    }
    float inv = 1.0f / (float)n;
    acc.x *= inv; acc.y *= inv; acc.z *= inv; acc.w *= inv;
    ((float4*)(g_vec + b * D))[t] = acc;

    float4 w = ((const float4*)(wattn + D))[t];
    float p = acc.x * w.x + acc.y * w.y + acc.z * w.z + acc.w * w.w;
    __shared__ float red[256];
    red[t] = p;
    __syncthreads();
    #pragma unroll
    for (int s = 128; s > 0; s >>= 1) {
        if (t < s) red[t] += red[t + s];
        __syncthreads();
    }
    if (t == 0) g_svec[b] = red[0];
}

// ---------------- softmax core (device inline) ----------------------------------
__device__ __forceinline__ void softmax_core(int b, int t, float svec, int len,
                                             float* red) {
    float sc = (t < len) ? tanhf(g_smb[b * L + t] + svec) : -1e30f;
    red[t] = sc;
    __syncthreads();
    #pragma unroll
    for (int s = 256; s > 0; s >>= 1) {
        if (t < s) red[t] = fmaxf(red[t], red[t + s]);
        __syncthreads();
    }
    float mx = red[0];
    __syncthreads();
    float e = expf(sc - mx);
    red[t] = e;
    __syncthreads();
    #pragma unroll
    for (int s = 256; s > 0; s >>= 1) {
        if (t < s) red[t] += red[t + s];
        __syncthreads();
    }
    float sm = red[0];
    g_aw[b * L + t] = (e / sm) * g_vloc[b * L + t];
}

// ---------------- kernel 3: standalone softmax (hop 0) --------------------------
__global__ void softmax_k(const float* __restrict__ battn,
                          const int* __restrict__ clen) {
    int b = blockIdx.x, t = threadIdx.x;
    __shared__ float red[L];
    softmax_core(b, t, g_svec[b] + battn[0], clen[b], red);
}

// ---------------- kernel 4: FUSED work: attn partials (bf16 staged) + lin GEMM --
// blocks [0, NATTN): attention; blocks [NATTN, NATTN+NLIN): lin split-K GEMM
__global__ void work_k(const int* __restrict__ clen,
                       const float* __restrict__ Wlin) {
    __shared__ float sh[16 * 65 + 16 * 64];   // lin tiles; attn reuses front
    int bid = blockIdx.x;
    int tid = threadIdx.x;

    if (bid < NATTN) {
        // ---- attention role: block = (b, ls), sequential bf16 reads ----
        int b = bid & (B - 1);
        int ls = bid >> 6;
        float* aw = sh;                 // [LCHUNK]
        float* part = sh + LCHUNK;      // [128*8] cross-group reduce buffer
        int l0 = ls * LCHUNK;
        if (tid < LCHUNK) aw[tid] = g_aw[b * L + l0 + tid];
        __syncthreads();

        int len = clen[b];
        int lend = len - l0;
        if (lend > LCHUNK) lend = LCHUNK;
        if (lend < 0) lend = 0;

        int grp = tid >> 7;        // 0 or 1: row parity
        int dt = tid & 127;        // d-slice: 8 bf16 elements each
        const uint4* base = (const uint4*)(g_mem + (size_t)(b * L + l0) * D) + dt;

        float acc[8] = {};
        #pragma unroll 4
        for (int l = grp; l < lend; l += 2) {
            float w = aw[l];
            uint4 q = base[l * 128];   // 128 uint4 per row (D*2B/16B)
            const __nv_bfloat162* h = (const __nv_bfloat162*)&q;
            float2 f0 = __bfloat1622float2(h[0]);
            float2 f1 = __bfloat1622float2(h[1]);
            float2 f2 = __bfloat1622float2(h[2]);
            float2 f3 = __bfloat1622float2(h[3]);
            acc[0] += w * f0.x; acc[1] += w * f0.y;
            acc[2] += w * f1.x; acc[3] += w * f1.y;
            acc[4] += w * f2.x; acc[5] += w * f2.y;
            acc[6] += w * f3.x; acc[7] += w * f3.y;
        }
        if (grp == 1) {
            #pragma unroll
            for (int j = 0; j < 8; j++) part[dt * 8 + j] = acc[j];
        }
        __syncthreads();
        if (grp == 0) {
            float* dst = g_attn_partial + ((long)ls * B + b) * D + dt * 8;
            float4 o0, o1;
            o0.x = acc[0] + part[dt * 8 + 0];
            o0.y = acc[1] + part[dt * 8 + 1];
            o0.z = acc[2] + part[dt * 8 + 2];
            o0.w = acc[3] + part[dt * 8 + 3];
            o1.x = acc[4] + part[dt * 8 + 4];
            o1.y = acc[5] + part[dt * 8 + 5];
            o1.z = acc[6] + part[dt * 8 + 6];
            o1.w = acc[7] + part[dt * 8 + 7];
            *(float4*)dst = o0;
            *(float4*)(dst + 4) = o1;
        }
    } else {
        // ---- lin GEMM role: 64x64 tile, split-K 16 ----
        int lb = bid - NATTN;
        int n0 = (lb & 15) * 64;
        int ks = lb >> 4;
        int kbase = ks * KCHUNK;
        float (*As)[65] = (float(*)[65])sh;
        float (*Bs)[64] = (float(*)[64])(sh + 16 * 65);
        int tx = tid & 15, ty = tid >> 4;

        float acc[4][4] = {};
        #pragma unroll
        for (int k0 = 0; k0 < KCHUNK; k0 += 16) {
            {
                int m = tid >> 2;
                int kq = (tid & 3) << 2;
                float4 av = *(const float4*)&g_vec[m * D + kbase + k0 + kq];
                As[kq + 0][m] = av.x;
                As[kq + 1][m] = av.y;
                As[kq + 2][m] = av.z;
                As[kq + 3][m] = av.w;
            }
            {
                int row = tid >> 4;
                int c4 = (tid & 15) << 2;
                float4 bv = *(const float4*)&Wlin[(long)(kbase + k0 + row) * D + n0 + c4];
                *(float4*)&Bs[row][c4] = bv;
            }
            __syncthreads();
            #pragma unroll
            for (int kk = 0; kk < 16; kk++) {
                float a[4], bb[4];
                #pragma unroll
                for (int i = 0; i < 4; i++) a[i] = As[kk][ty * 4 + i];
                float4 bv = *(const float4*)&Bs[kk][tx * 4];
                bb[0] = bv.x; bb[1] = bv.y; bb[2] = bv.z; bb[3] = bv.w;
                #pragma unroll
                for (int i = 0; i < 4; i++)
                    #pragma unroll
                    for (int j = 0; j < 4; j++)
                        acc[i][j] += a[i] * bb[j];
            }
            __syncthreads();
        }
        #pragma unroll
        for (int i = 0; i < 4; i++) {
            int m = ty * 4 + i;
            #pragma unroll
            for (int j = 0; j < 4; j++) {
                g_lin_partial[((long)ks * B + m) * D + n0 + tx * 4 + j] = acc[i][j];
            }
        }
    }
}

// ---------------- combine core: partials -> vec (2 floats per thread) -----------
__device__ __forceinline__ float2 combine_core(int b, int t, const float* blin) {
    int d = t * 2;
    float2 v = *(const float2*)(blin + d);
    #pragma unroll
    for (int ls = 0; ls < LS; ls++) {
        float2 p = *(const float2*)(g_attn_partial + ((long)ls * B + b) * D + d);
        v.x += p.x; v.y += p.y;
    }
    #pragma unroll
    for (int ks = 0; ks < KSPLIT; ks++) {
        float2 p = *(const float2*)(g_lin_partial + ((long)ks * B + b) * D + d);
        v.x += p.x; v.y += p.y;
    }
    *(float2*)(g_vec + b * D + d) = v;
    return v;
}

// ---------------- kernel 5: fused combine + softmax (hops 0..4) -----------------
__global__ void combine_softmax_k(const float* __restrict__ blin,
                                  const float* __restrict__ wattn,
                                  const float* __restrict__ battn,
                                  const int* __restrict__ clen) {
    int b = blockIdx.x, t = threadIdx.x;
    __shared__ float red[L];

    float2 v = combine_core(b, t, blin);

    int d = t * 2;
    float2 w = *(const float2*)(wattn + D + d);
    red[t] = v.x * w.x + v.y * w.y;
    __syncthreads();
    #pragma unroll
    for (int s = 256; s > 0; s >>= 1) {
        if (t < s) red[t] += red[t + s];
        __syncthreads();
    }
    float svec = red[0] + battn[0];
    __syncthreads();

    softmax_core(b, t, svec, clen[b], red);
}

// ---------------- kernel 6: fused combine + output logits (last hop) ------------
__global__ void combine_out_k(const float* __restrict__ blin,
                              const float* __restrict__ Wout,
                              const float* __restrict__ bout,
                              float* __restrict__ out) {
    int b = blockIdx.x, t = threadIdx.x;
    float2 v = combine_core(b, t, blin);

    int d = t * 2;
    float p0 = v.x * Wout[d * C + 0] + v.y * Wout[(d + 1) * C + 0];
    float p1 = v.x * Wout[d * C + 1] + v.y * Wout[(d + 1) * C + 1];
    float p2 = v.x * Wout[d * C + 2] + v.y * Wout[(d + 1) * C + 2];

    __shared__ float r[C][512];
    r[0][t] = p0; r[1][t] = p1; r[2][t] = p2;
    __syncthreads();
    #pragma unroll
    for (int s = 256; s > 0; s >>= 1) {
        if (t < s) {
            r[0][t] += r[0][t + s];
            r[1][t] += r[1][t + s];
            r[2][t] += r[2][t + s];
        }
        __syncthreads();
    }
    if (t < C) out[b * C + t] = r[t][0] + bout[t];
}

// ---------------- launcher -------------------------------------------------------
extern "C" void kernel_launch(void* const* d_in, const int* in_sizes, int n_in,
                              void* d_out, int out_size) {
    const int*   ctx   = (const int*)d_in[0];
    const int*   tgt   = (const int*)d_in[1];
    const int*   clen  = (const int*)d_in[2];
    const int*   tlen  = (const int*)d_in[3];
    const int*   toff  = (const int*)d_in[4];
    const float* emb   = (const float*)d_in[5];
    const float* Wlin  = (const float*)d_in[6];
    const float* blin  = (const float*)d_in[7];
    const float* wattn = (const float*)d_in[8];
    const float* battn = (const float*)d_in[9];
    const float* Wout  = (const float*)d_in[10];
    const float* bout  = (const float*)d_in[11];
    float* out = (float*)d_out;

    precompute_k<<<dim3(B, L / 8), 256>>>(ctx, clen, toff, emb, wattn);
    vaspect_k<<<B, 256>>>(tgt, tlen, emb, wattn);
    softmax_k<<<B, L>>>(battn, clen);

    for (int h = 0; h < N_HOPS; h++) {
        work_k<<<NATTN + NLIN, 256>>>(clen, Wlin);
        if (h < N_HOPS - 1)
            combine_softmax_k<<<B, L>>>(blin, wattn, battn, clen);
        else
            combine_out_k<<<B, L>>>(blin, Wout, bout, out);
    }
}